// round 13
// baseline (speedup 1.0000x reference)
#include <cuda_runtime.h>
#include <cstdint>

// ---------------- problem constants ----------------
#define T_TOK   8192
#define DMODEL  1024
#define NEXP    8
#define DFFN    4096
#define CAPCT   1280            // int(1.25*8192/8), even, >= 4
#define NSLOT   (NEXP*CAPCT)    // 10240

// ---------------- persistent scratch (device globals; no allocs) ----------------
__device__ int   g_top1[T_TOK];
__device__ float g_prob[T_TOK];
__device__ float g_me[NEXP];
__device__ int   g_kept[T_TOK];                  // 1 if token kept (rank < cap)
__device__ int   g_slot_tok[NSLOT];
__device__ float g_slot_w[NSLOT];
__device__ int   g_cnt_cap[NEXP];
__device__ float g_xd[(size_t)NSLOT * DMODEL];   // dispatched tokens, tf32-rounded
__device__ float g_h[(size_t)NSLOT * DFFN];      // GEMM1 output (gelu'd, tf32-rounded)

// ---------------- small helpers ----------------
__device__ __forceinline__ uint32_t f2tf(float f) {
    uint32_t r; asm("cvt.rna.tf32.f32 %0, %1;" : "=r"(r) : "f"(f)); return r;
}
__device__ __forceinline__ void cp16(uint32_t dst, const void* src) {
    asm volatile("cp.async.cg.shared.global [%0], [%1], 16;" :: "r"(dst), "l"(src));
}
__device__ __forceinline__ void cp_commit() { asm volatile("cp.async.commit_group;"); }
__device__ __forceinline__ void cp_wait2()  { asm volatile("cp.async.wait_group 2;"); }

__device__ __forceinline__ void mma_tf32(float* c, const uint32_t* a, uint32_t b0, uint32_t b1) {
    asm volatile(
        "mma.sync.aligned.m16n8k8.row.col.f32.tf32.tf32.f32 "
        "{%0,%1,%2,%3},{%4,%5,%6,%7},{%8,%9},{%0,%1,%2,%3};"
        : "+f"(c[0]), "+f"(c[1]), "+f"(c[2]), "+f"(c[3])
        : "r"(a[0]), "r"(a[1]), "r"(a[2]), "r"(a[3]), "r"(b0), "r"(b1));
}

__device__ __forceinline__ float gelu_f(float x) {
    float u = 0.7978845608028654f * (x + 0.044715f * x * x * x);
    float e = __expf(2.f * u);
    float t = 1.f - 2.f / (e + 1.f);
    return 0.5f * x * (1.f + t);
}

// ---------------- kernel 0a: init me accumulators ----------------
__global__ void init_me_kernel() {
    if (threadIdx.x < NEXP) g_me[threadIdx.x] = 0.f;
}

// ---------------- kernel 0b: zero only dropped-token rows (after scan) ----------------
__global__ __launch_bounds__(256) void zero_dropped_kernel(float* __restrict__ out) {
    int w = (blockIdx.x * blockDim.x + threadIdx.x) >> 5;   // one warp per token
    int lane = threadIdx.x & 31;
    if (w >= T_TOK || g_kept[w]) return;
    float4* row = (float4*)(out + (size_t)w * DMODEL);
    float4 z = make_float4(0.f, 0.f, 0.f, 0.f);
#pragma unroll
    for (int i = 0; i < 8; i++) row[lane + 32 * i] = z;
}

// ---------------- kernel 1: gating (1 warp per token) ----------------
__global__ __launch_bounds__(256) void gating_kernel(
    const float* __restrict__ tokens, const float* __restrict__ gw) {
    __shared__ float4 sgw[NEXP * 256];
    __shared__ float sme[NEXP];
    int tid = threadIdx.x;
    const float4* gw4 = (const float4*)gw;
    for (int i = tid; i < NEXP * 256; i += 256) sgw[i] = gw4[i];
    if (tid < NEXP) sme[tid] = 0.f;
    __syncthreads();

    int warp = tid >> 5, lane = tid & 31;
    int t = blockIdx.x * 8 + warp;
    const float4* tok = (const float4*)(tokens + (size_t)t * DMODEL);

    float acc[NEXP];
#pragma unroll
    for (int e = 0; e < NEXP; e++) acc[e] = 0.f;
#pragma unroll
    for (int j = 0; j < 8; j++) {
        float4 x = tok[lane + 32 * j];
#pragma unroll
        for (int e = 0; e < NEXP; e++) {
            float4 w = sgw[e * 256 + lane + 32 * j];
            acc[e] += x.x * w.x + x.y * w.y + x.z * w.z + x.w * w.w;
        }
    }
#pragma unroll
    for (int off = 16; off; off >>= 1)
#pragma unroll
        for (int e = 0; e < NEXP; e++)
            acc[e] += __shfl_xor_sync(0xffffffffu, acc[e], off);

    if (lane == 0) {
        float mx = acc[0]; int am = 0;
#pragma unroll
        for (int e = 1; e < NEXP; e++) if (acc[e] > mx) { mx = acc[e]; am = e; }
        float p[NEXP], s = 0.f;
#pragma unroll
        for (int e = 0; e < NEXP; e++) { p[e] = expf(acc[e] - mx); s += p[e]; }
        float inv = 1.f / s;
        g_top1[t] = am;
        g_prob[t] = p[am] * inv;
#pragma unroll
        for (int e = 0; e < NEXP; e++) atomicAdd(&sme[e], p[e] * inv);
    }
    __syncthreads();
    if (tid < NEXP) atomicAdd(&g_me[tid], sme[tid]);
}

// ---------------- kernel 2: routing scan (single block, exact cumsum order) ----------------
__global__ __launch_bounds__(1024) void scan_kernel(float* __restrict__ out, int out_size) {
    __shared__ int sh_wc[NEXP][32];
    __shared__ int sh_base[NEXP];
    __shared__ int sh_tot[NEXP];
    int tid = threadIdx.x, warp = tid >> 5, lane = tid & 31;
    unsigned ltmask = (1u << lane) - 1u;
    if (tid < NEXP) sh_base[tid] = 0;
    __syncthreads();

    for (int tile = 0; tile < T_TOK / 1024; tile++) {
        int t = tile * 1024 + tid;
        int e = g_top1[t];
        int rank_w = 0;
#pragma unroll
        for (int e8 = 0; e8 < NEXP; e8++) {
            unsigned m = __ballot_sync(0xffffffffu, e == e8);
            if (e == e8) rank_w = __popc(m & ltmask);
            if (lane == 0) sh_wc[e8][warp] = __popc(m);
        }
        __syncthreads();
        if (warp < NEXP) {
            int c = sh_wc[warp][lane];
            int s = c;
#pragma unroll
            for (int off = 1; off < 32; off <<= 1) {
                int v = __shfl_up_sync(0xffffffffu, s, off);
                if (lane >= off) s += v;
            }
            sh_wc[warp][lane] = s - c;
            if (lane == 31) sh_tot[warp] = s;
        }
        __syncthreads();
        int rank = sh_base[e] + sh_wc[e][warp] + rank_w;
        if (rank < CAPCT) {
            int slot = e * CAPCT + rank;
            g_slot_tok[slot] = t;
            g_slot_w[slot] = g_prob[t];
            g_kept[t] = 1;
        } else {
            g_kept[t] = 0;
        }
        __syncthreads();
        if (tid < NEXP) sh_base[tid] += sh_tot[tid];
        __syncthreads();
    }

    if (tid < NEXP) g_cnt_cap[tid] = min(sh_base[tid], CAPCT);
    __syncthreads();
    for (int i = tid; i < NSLOT; i += 1024) {
        int e = i / CAPCT, r = i - e * CAPCT;
        if (r >= min(sh_base[e], CAPCT)) { g_slot_tok[i] = -1; g_slot_w[i] = 0.f; }
    }
    if (tid == 0 && out_size > T_TOK * DMODEL) {
        float la = 0.f;
        const float invT = 1.f / (float)T_TOK;
#pragma unroll
        for (int e = 0; e < NEXP; e++)
            la += (g_me[e] * invT) * ((float)sh_base[e] * invT);
        out[T_TOK * DMODEL] = (float)NEXP * la;
    }
}

// ---------------- kernel 3: dispatch gather (tf32-rounded) ----------------
__global__ __launch_bounds__(256) void dispatch_kernel(const float* __restrict__ tokens) {
    int slot = blockIdx.x;
    int tok = g_slot_tok[slot];
    uint4* dst = (uint4*)(g_xd + (size_t)slot * DMODEL);
    if (tok < 0) {
        dst[threadIdx.x] = make_uint4(0u, 0u, 0u, 0u);
    } else {
        const float4* src = (const float4*)(tokens + (size_t)tok * DMODEL);
        float4 v = src[threadIdx.x];
        dst[threadIdx.x] = make_uint4(f2tf(v.x), f2tf(v.y), f2tf(v.z), f2tf(v.w));
    }
}

// ---- GEMM: 64x128x16 CTA tile, 32x32 warp tile (2x4 warps), 4-stage cp.async ----
// 3 CTAs/SM (measured optimum, R11). Deeper pipeline for the shared issue slots.
#define BM 64
#define BN 128
#define BK 16
#define AST 20                   // padded A row stride (floats)
#define BST 136                  // padded B row stride (floats)
#define SA_STAGE (BM*AST)        // 1280 floats
#define SB_STAGE (BK*BST)        // 2176 floats
#define GSTAGES 4                // 55296 B static shared; x3 CTAs = 166 KB < 228 KB

// MODE 1: h = gelu(g_xd @ w1 + b1)         (K=1024, N=4096)
// MODE 2: out[token] = w * (g_h @ w2 + b2) (K=4096, N=1024), scatter
template <int MODE>
__global__ __launch_bounds__(256, 3) void ffn_gemm(
    const float* __restrict__ Wbase,
    const float* __restrict__ biasBase, float* __restrict__ Obase) {
    constexpr int N = (MODE == 1) ? DFFN : DMODEL;
    constexpr int K = (MODE == 1) ? DMODEL : DFFN;
    constexpr int KT = K / BK;

    const float* Abase = (MODE == 1) ? g_xd : g_h;   // device-side symbol ref
    constexpr int AROWSTRIDE = (MODE == 1) ? DMODEL : DFFN;

    const int e = blockIdx.z;
    const int mtile = blockIdx.y;
    const int ntile = blockIdx.x;
    if (mtile * BM >= g_cnt_cap[e]) return;

    __shared__ __align__(16) float sA[GSTAGES][SA_STAGE];
    __shared__ __align__(16) float sB[GSTAGES][SB_STAGE];
    uint32_t sA32 = (uint32_t)__cvta_generic_to_shared(&sA[0][0]);
    uint32_t sB32 = (uint32_t)__cvta_generic_to_shared(&sB[0][0]);

    const int tid = threadIdx.x;
    const int lane = tid & 31, warp = tid >> 5;
    const int wm = warp >> 2, wn = warp & 3;      // 2x4 warp grid: 32x32 per warp
    const int g = lane >> 2, tig = lane & 3;

    const float* W = Wbase + (size_t)e * K * N;
    const float* bias = biasBase + (size_t)e * N;
    const int slot0 = e * CAPCT + mtile * BM;

    // ---- producer assignments ----
    const int akc = tid & 3;
    const int arow = tid >> 2;
    const float* asrc = Abase + (size_t)(slot0 + arow) * AROWSTRIDE + akc * 4;
    const uint32_t adst = sA32 + (arow * AST + akc * 4) * 4;
    const int bc = tid & 31;
    const float* bsrc[2]; uint32_t bdst[2];
#pragma unroll
    for (int i = 0; i < 2; i++) {
        int brow = (tid >> 5) + i * 8;
        bsrc[i] = W + (size_t)brow * N + ntile * BN + bc * 4;
        bdst[i] = sB32 + (brow * BST + bc * 4) * 4;
    }

    auto issue = [&](int kt) {
        const int stage = kt & (GSTAGES - 1);
        uint32_t ao = stage * (SA_STAGE * 4);
        uint32_t bo = stage * (SB_STAGE * 4);
        size_t kA = (size_t)kt * BK;
        size_t kB = (size_t)kt * BK * N;
        cp16(adst + ao, asrc + kA);
        cp16(bdst[0] + bo, bsrc[0] + kB);
        cp16(bdst[1] + bo, bsrc[1] + kB);
        cp_commit();
    };

    float acc[2][4][4];
#pragma unroll
    for (int mt = 0; mt < 2; mt++)
#pragma unroll
        for (int nt = 0; nt < 4; nt++)
#pragma unroll
            for (int c = 0; c < 4; c++) acc[mt][nt][c] = 0.f;

    issue(0); issue(1); issue(2);

    for (int kt = 0; kt < KT; kt++) {
        cp_wait2();
        __syncthreads();
        int nx = kt + 3;
        if (nx < KT) issue(nx);
        else cp_commit();   // keep group count consistent for wait_group

        const int cur = kt & (GSTAGES - 1);
        const uint32_t* As = (const uint32_t*)&sA[cur][0];
        const uint32_t* Bs = (const uint32_t*)&sB[cur][0];
#pragma unroll
        for (int ks = 0; ks < 2; ks++) {
            uint32_t af[2][4];
#pragma unroll
            for (int mt = 0; mt < 2; mt++) {
                const uint32_t* p = As + (wm * 32 + mt * 16 + g) * AST + ks * 8 + tig;
                af[mt][0] = p[0];
                af[mt][1] = p[8 * AST];
                af[mt][2] = p[4];
                af[mt][3] = p[8 * AST + 4];
            }
#pragma unroll
            for (int nt = 0; nt < 4; nt++) {
                const uint32_t* p = Bs + (ks * 8 + tig) * BST + wn * 32 + nt * 8 + g;
                uint32_t b0 = p[0];
                uint32_t b1 = p[4 * BST];
                mma_tf32(acc[0][nt], af[0], b0, b1);
                mma_tf32(acc[1][nt], af[1], b0, b1);
            }
        }
    }

    // ---- epilogue ----
    if (MODE == 1) {
#pragma unroll
        for (int mt = 0; mt < 2; mt++)
#pragma unroll
            for (int half = 0; half < 2; half++) {
                int rloc = wm * 32 + mt * 16 + g + half * 8;
                float* hrow = g_h + (size_t)(slot0 + rloc) * DFFN;
#pragma unroll
                for (int nt = 0; nt < 4; nt++) {
                    int col = ntile * BN + wn * 32 + nt * 8 + 2 * tig;
                    float2 bb = *(const float2*)(bias + col);
                    float v0 = gelu_f(acc[mt][nt][half * 2 + 0] + bb.x);
                    float v1 = gelu_f(acc[mt][nt][half * 2 + 1] + bb.y);
                    // pre-round h to tf32 so GEMM2's consumer needs no cvt
                    *(uint2*)(hrow + col) = make_uint2(f2tf(v0), f2tf(v1));
                }
            }
    } else {
#pragma unroll
        for (int mt = 0; mt < 2; mt++)
#pragma unroll
            for (int half = 0; half < 2; half++) {
                int rloc = wm * 32 + mt * 16 + g + half * 8;
                int slot = slot0 + rloc;
                int tok = g_slot_tok[slot];
                if (tok >= 0) {
                    float w = g_slot_w[slot];
                    float* orow = Obase + (size_t)tok * DMODEL;
#pragma unroll
                    for (int nt = 0; nt < 4; nt++) {
                        int col = ntile * BN + wn * 32 + nt * 8 + 2 * tig;
                        float2 bb = *(const float2*)(bias + col);
                        float v0 = (acc[mt][nt][half * 2 + 0] + bb.x) * w;
                        float v1 = (acc[mt][nt][half * 2 + 1] + bb.y) * w;
                        *(float2*)(orow + col) = make_float2(v0, v1);
                    }
                }
            }
    }
}

// ---------------- launch ----------------
extern "C" void kernel_launch(void* const* d_in, const int* in_sizes, int n_in,
                              void* d_out, int out_size) {
    const float* inputs = (const float*)d_in[0];
    const float* gatew  = (const float*)d_in[1];
    const float* w1     = (const float*)d_in[2];
    const float* b1     = (const float*)d_in[3];
    const float* w2     = (const float*)d_in[4];
    const float* b2     = (const float*)d_in[5];
    float* out = (float*)d_out;

    init_me_kernel<<<1, 32>>>();
    gating_kernel<<<T_TOK / 8, 256>>>(inputs, gatew);
    scan_kernel<<<1, 1024>>>(out, out_size);
    zero_dropped_kernel<<<T_TOK * 32 / 256, 256>>>(out);
    dispatch_kernel<<<NSLOT, 256>>>(inputs);
    ffn_gemm<1><<<dim3(DFFN / BN, CAPCT / BM, NEXP), 256>>>(w1, b1, nullptr);
    ffn_gemm<2><<<dim3(DMODEL / BN, CAPCT / BM, NEXP), 256>>>(w2, b2, out);
}

// round 14
// speedup vs baseline: 1.0373x; 1.0373x over previous
#include <cuda_runtime.h>
#include <cstdint>

// ---------------- problem constants ----------------
#define T_TOK   8192
#define DMODEL  1024
#define NEXP    8
#define DFFN    4096
#define CAPCT   1280            // int(1.25*8192/8), even, >= 4
#define NSLOT   (NEXP*CAPCT)    // 10240

// ---------------- persistent scratch (device globals; no allocs) ----------------
__device__ int   g_top1[T_TOK];
__device__ float g_prob[T_TOK];
__device__ float g_me[NEXP];
__device__ int   g_kept[T_TOK];                  // 1 if token kept (rank < cap)
__device__ int   g_slot_tok[NSLOT];
__device__ float g_slot_w[NSLOT];
__device__ int   g_cnt_cap[NEXP];
__device__ float g_h[(size_t)NSLOT * DFFN];      // GEMM1 output (gelu'd, tf32-rounded)

// ---------------- small helpers ----------------
__device__ __forceinline__ uint32_t f2tf(float f) {
    uint32_t r; asm("cvt.rna.tf32.f32 %0, %1;" : "=r"(r) : "f"(f)); return r;
}
__device__ __forceinline__ void cp16(uint32_t dst, const void* src) {
    asm volatile("cp.async.cg.shared.global [%0], [%1], 16;" :: "r"(dst), "l"(src));
}
// zfill variant: sz=0 -> writes zeros to smem (used for empty slots)
__device__ __forceinline__ void cp16z(uint32_t dst, const void* src, int sz) {
    asm volatile("cp.async.cg.shared.global [%0], [%1], 16, %2;"
                 :: "r"(dst), "l"(src), "r"(sz));
}
__device__ __forceinline__ void cp_commit() { asm volatile("cp.async.commit_group;"); }
__device__ __forceinline__ void cp_wait1()  { asm volatile("cp.async.wait_group 1;"); }

__device__ __forceinline__ void mma_tf32(float* c, const uint32_t* a, uint32_t b0, uint32_t b1) {
    asm volatile(
        "mma.sync.aligned.m16n8k8.row.col.f32.tf32.tf32.f32 "
        "{%0,%1,%2,%3},{%4,%5,%6,%7},{%8,%9},{%0,%1,%2,%3};"
        : "+f"(c[0]), "+f"(c[1]), "+f"(c[2]), "+f"(c[3])
        : "r"(a[0]), "r"(a[1]), "r"(a[2]), "r"(a[3]), "r"(b0), "r"(b1));
}

__device__ __forceinline__ float gelu_f(float x) {
    float u = 0.7978845608028654f * (x + 0.044715f * x * x * x);
    float e = __expf(2.f * u);
    float t = 1.f - 2.f / (e + 1.f);
    return 0.5f * x * (1.f + t);
}

// ---------------- kernel 0a: init me accumulators ----------------
__global__ void init_me_kernel() {
    if (threadIdx.x < NEXP) g_me[threadIdx.x] = 0.f;
}

// ---------------- kernel 0b: zero only dropped-token rows (after scan) ----------------
__global__ __launch_bounds__(256) void zero_dropped_kernel(float* __restrict__ out) {
    int w = (blockIdx.x * blockDim.x + threadIdx.x) >> 5;   // one warp per token
    int lane = threadIdx.x & 31;
    if (w >= T_TOK || g_kept[w]) return;
    float4* row = (float4*)(out + (size_t)w * DMODEL);
    float4 z = make_float4(0.f, 0.f, 0.f, 0.f);
#pragma unroll
    for (int i = 0; i < 8; i++) row[lane + 32 * i] = z;
}

// ---------------- kernel 1: gating (1 warp per token) ----------------
__global__ __launch_bounds__(256) void gating_kernel(
    const float* __restrict__ tokens, const float* __restrict__ gw) {
    __shared__ float4 sgw[NEXP * 256];
    __shared__ float sme[NEXP];
    int tid = threadIdx.x;
    const float4* gw4 = (const float4*)gw;
    for (int i = tid; i < NEXP * 256; i += 256) sgw[i] = gw4[i];
    if (tid < NEXP) sme[tid] = 0.f;
    __syncthreads();

    int warp = tid >> 5, lane = tid & 31;
    int t = blockIdx.x * 8 + warp;
    const float4* tok = (const float4*)(tokens + (size_t)t * DMODEL);

    float acc[NEXP];
#pragma unroll
    for (int e = 0; e < NEXP; e++) acc[e] = 0.f;
#pragma unroll
    for (int j = 0; j < 8; j++) {
        float4 x = tok[lane + 32 * j];
#pragma unroll
        for (int e = 0; e < NEXP; e++) {
            float4 w = sgw[e * 256 + lane + 32 * j];
            acc[e] += x.x * w.x + x.y * w.y + x.z * w.z + x.w * w.w;
        }
    }
#pragma unroll
    for (int off = 16; off; off >>= 1)
#pragma unroll
        for (int e = 0; e < NEXP; e++)
            acc[e] += __shfl_xor_sync(0xffffffffu, acc[e], off);

    if (lane == 0) {
        float mx = acc[0]; int am = 0;
#pragma unroll
        for (int e = 1; e < NEXP; e++) if (acc[e] > mx) { mx = acc[e]; am = e; }
        float p[NEXP], s = 0.f;
#pragma unroll
        for (int e = 0; e < NEXP; e++) { p[e] = expf(acc[e] - mx); s += p[e]; }
        float inv = 1.f / s;
        g_top1[t] = am;
        g_prob[t] = p[am] * inv;
#pragma unroll
        for (int e = 0; e < NEXP; e++) atomicAdd(&sme[e], p[e] * inv);
    }
    __syncthreads();
    if (tid < NEXP) atomicAdd(&g_me[tid], sme[tid]);
}

// ---------------- kernel 2: routing scan (single block, exact cumsum order) ----------------
__global__ __launch_bounds__(1024) void scan_kernel(float* __restrict__ out, int out_size) {
    __shared__ int sh_wc[NEXP][32];
    __shared__ int sh_base[NEXP];
    __shared__ int sh_tot[NEXP];
    int tid = threadIdx.x, warp = tid >> 5, lane = tid & 31;
    unsigned ltmask = (1u << lane) - 1u;
    if (tid < NEXP) sh_base[tid] = 0;
    __syncthreads();

    for (int tile = 0; tile < T_TOK / 1024; tile++) {
        int t = tile * 1024 + tid;
        int e = g_top1[t];
        int rank_w = 0;
#pragma unroll
        for (int e8 = 0; e8 < NEXP; e8++) {
            unsigned m = __ballot_sync(0xffffffffu, e == e8);
            if (e == e8) rank_w = __popc(m & ltmask);
            if (lane == 0) sh_wc[e8][warp] = __popc(m);
        }
        __syncthreads();
        if (warp < NEXP) {
            int c = sh_wc[warp][lane];
            int s = c;
#pragma unroll
            for (int off = 1; off < 32; off <<= 1) {
                int v = __shfl_up_sync(0xffffffffu, s, off);
                if (lane >= off) s += v;
            }
            sh_wc[warp][lane] = s - c;
            if (lane == 31) sh_tot[warp] = s;
        }
        __syncthreads();
        int rank = sh_base[e] + sh_wc[e][warp] + rank_w;
        if (rank < CAPCT) {
            int slot = e * CAPCT + rank;
            g_slot_tok[slot] = t;
            g_slot_w[slot] = g_prob[t];
            g_kept[t] = 1;
        } else {
            g_kept[t] = 0;
        }
        __syncthreads();
        if (tid < NEXP) sh_base[tid] += sh_tot[tid];
        __syncthreads();
    }

    if (tid < NEXP) g_cnt_cap[tid] = min(sh_base[tid], CAPCT);
    __syncthreads();
    for (int i = tid; i < NSLOT; i += 1024) {
        int e = i / CAPCT, r = i - e * CAPCT;
        if (r >= min(sh_base[e], CAPCT)) { g_slot_tok[i] = -1; g_slot_w[i] = 0.f; }
    }
    if (tid == 0 && out_size > T_TOK * DMODEL) {
        float la = 0.f;
        const float invT = 1.f / (float)T_TOK;
#pragma unroll
        for (int e = 0; e < NEXP; e++)
            la += (g_me[e] * invT) * ((float)sh_base[e] * invT);
        out[T_TOK * DMODEL] = (float)NEXP * la;
    }
}

// ---- GEMM: 64x128x16 CTA tile, 32x32 warp tile (2x4 warps), 3-stage cp.async ----
// Exact R11 config (measured optimum: 3 CTAs/SM, wait_group 1). MODE 1 gathers
// token rows directly (dispatch fused into producer; cvt.rna on A in consumer).
#define BM 64
#define BN 128
#define BK 16
#define AST 20                   // padded A row stride (floats)
#define BST 136                  // padded B row stride (floats)
#define SA_STAGE (BM*AST)        // 1280 floats
#define SB_STAGE (BK*BST)        // 2176 floats
#define GSTAGES 3                // 41472 B static shared

// MODE 1: h = gelu(gather(tokens) @ w1 + b1)  (K=1024, N=4096)
// MODE 2: out[token] = w * (g_h @ w2 + b2)    (K=4096, N=1024), scatter
template <int MODE>
__global__ __launch_bounds__(256, 3) void ffn_gemm(
    const float* __restrict__ Atokens,          // tokens (MODE 1); unused in MODE 2
    const float* __restrict__ Wbase,
    const float* __restrict__ biasBase, float* __restrict__ Obase) {
    constexpr int N = (MODE == 1) ? DFFN : DMODEL;
    constexpr int K = (MODE == 1) ? DMODEL : DFFN;
    constexpr int KT = K / BK;

    const int e = blockIdx.z;
    const int mtile = blockIdx.y;
    const int ntile = blockIdx.x;
    if (mtile * BM >= g_cnt_cap[e]) return;

    __shared__ __align__(16) float sA[GSTAGES][SA_STAGE];
    __shared__ __align__(16) float sB[GSTAGES][SB_STAGE];
    uint32_t sA32 = (uint32_t)__cvta_generic_to_shared(&sA[0][0]);
    uint32_t sB32 = (uint32_t)__cvta_generic_to_shared(&sB[0][0]);

    const int tid = threadIdx.x;
    const int lane = tid & 31, warp = tid >> 5;
    const int wm = warp >> 2, wn = warp & 3;      // 2x4 warp grid: 32x32 per warp
    const int g = lane >> 2, tig = lane & 3;

    const float* W = Wbase + (size_t)e * K * N;
    const float* bias = biasBase + (size_t)e * N;
    const int slot0 = e * CAPCT + mtile * BM;

    // ---- producer assignments ----
    const int akc = tid & 3;
    const int arow = tid >> 2;
    const float* asrc;
    int asz = 16;
    if (MODE == 1) {
        int tok = g_slot_tok[slot0 + arow];
        asz = (tok < 0) ? 0 : 16;                 // zfill empty slots
        asrc = Atokens + (size_t)(tok < 0 ? 0 : tok) * DMODEL + akc * 4;
    } else {
        asrc = g_h + (size_t)(slot0 + arow) * DFFN + akc * 4;
    }
    const uint32_t adst = sA32 + (arow * AST + akc * 4) * 4;
    const int bc = tid & 31;
    const float* bsrc[2]; uint32_t bdst[2];
#pragma unroll
    for (int i = 0; i < 2; i++) {
        int brow = (tid >> 5) + i * 8;
        bsrc[i] = W + (size_t)brow * N + ntile * BN + bc * 4;
        bdst[i] = sB32 + (brow * BST + bc * 4) * 4;
    }

    auto issue = [&](int kt, int stage) {
        uint32_t ao = stage * (SA_STAGE * 4);
        uint32_t bo = stage * (SB_STAGE * 4);
        size_t kA = (size_t)kt * BK;
        size_t kB = (size_t)kt * BK * N;
        if (MODE == 1) cp16z(adst + ao, asrc + kA, asz);
        else           cp16(adst + ao, asrc + kA);
        cp16(bdst[0] + bo, bsrc[0] + kB);
        cp16(bdst[1] + bo, bsrc[1] + kB);
    };

    float acc[2][4][4];
#pragma unroll
    for (int mt = 0; mt < 2; mt++)
#pragma unroll
        for (int nt = 0; nt < 4; nt++)
#pragma unroll
            for (int c = 0; c < 4; c++) acc[mt][nt][c] = 0.f;

    issue(0, 0); cp_commit();
    issue(1, 1); cp_commit();

    int cur = 0, nxst = 2;
    for (int kt = 0; kt < KT; kt++) {
        cp_wait1();
        __syncthreads();
        int nx = kt + 2;
        if (nx < KT) issue(nx, nxst);
        cp_commit();

        const float*    Asf = &sA[cur][0];
        const uint32_t* Bs  = (const uint32_t*)&sB[cur][0];
#pragma unroll
        for (int ks = 0; ks < 2; ks++) {
            uint32_t af[2][4];
#pragma unroll
            for (int mt = 0; mt < 2; mt++) {
                const float* p = Asf + (wm * 32 + mt * 16 + g) * AST + ks * 8 + tig;
                if (MODE == 1) {
                    // A gathered raw f32 -> round here (same values as a
                    // pre-rounded dispatch buffer; numerics identical)
                    af[mt][0] = f2tf(p[0]);
                    af[mt][1] = f2tf(p[8 * AST]);
                    af[mt][2] = f2tf(p[4]);
                    af[mt][3] = f2tf(p[8 * AST + 4]);
                } else {
                    const uint32_t* q = (const uint32_t*)p;
                    af[mt][0] = q[0];
                    af[mt][1] = q[8 * AST];
                    af[mt][2] = q[4];
                    af[mt][3] = q[8 * AST + 4];
                }
            }
#pragma unroll
            for (int nt = 0; nt < 4; nt++) {
                const uint32_t* p = Bs + (ks * 8 + tig) * BST + wn * 32 + nt * 8 + g;
                uint32_t b0 = p[0];
                uint32_t b1 = p[4 * BST];
                mma_tf32(acc[0][nt], af[0], b0, b1);
                mma_tf32(acc[1][nt], af[1], b0, b1);
            }
        }
        cur = (cur == GSTAGES - 1) ? 0 : cur + 1;
        nxst = (nxst == GSTAGES - 1) ? 0 : nxst + 1;
    }

    // ---- epilogue ----
    if (MODE == 1) {
#pragma unroll
        for (int mt = 0; mt < 2; mt++)
#pragma unroll
            for (int half = 0; half < 2; half++) {
                int rloc = wm * 32 + mt * 16 + g + half * 8;
                float* hrow = g_h + (size_t)(slot0 + rloc) * DFFN;
#pragma unroll
                for (int nt = 0; nt < 4; nt++) {
                    int col = ntile * BN + wn * 32 + nt * 8 + 2 * tig;
                    float2 bb = *(const float2*)(bias + col);
                    float v0 = gelu_f(acc[mt][nt][half * 2 + 0] + bb.x);
                    float v1 = gelu_f(acc[mt][nt][half * 2 + 1] + bb.y);
                    // pre-round h to tf32 so GEMM2's consumer needs no cvt
                    *(uint2*)(hrow + col) = make_uint2(f2tf(v0), f2tf(v1));
                }
            }
    } else {
#pragma unroll
        for (int mt = 0; mt < 2; mt++)
#pragma unroll
            for (int half = 0; half < 2; half++) {
                int rloc = wm * 32 + mt * 16 + g + half * 8;
                int slot = slot0 + rloc;
                int tok = g_slot_tok[slot];
                if (tok >= 0) {
                    float w = g_slot_w[slot];
                    float* orow = Obase + (size_t)tok * DMODEL;
#pragma unroll
                    for (int nt = 0; nt < 4; nt++) {
                        int col = ntile * BN + wn * 32 + nt * 8 + 2 * tig;
                        float2 bb = *(const float2*)(bias + col);
                        float v0 = (acc[mt][nt][half * 2 + 0] + bb.x) * w;
                        float v1 = (acc[mt][nt][half * 2 + 1] + bb.y) * w;
                        *(float2*)(orow + col) = make_float2(v0, v1);
                    }
                }
            }
    }
}

// ---------------- launch ----------------
extern "C" void kernel_launch(void* const* d_in, const int* in_sizes, int n_in,
                              void* d_out, int out_size) {
    const float* inputs = (const float*)d_in[0];
    const float* gatew  = (const float*)d_in[1];
    const float* w1     = (const float*)d_in[2];
    const float* b1     = (const float*)d_in[3];
    const float* w2     = (const float*)d_in[4];
    const float* b2     = (const float*)d_in[5];
    float* out = (float*)d_out;

    init_me_kernel<<<1, 32>>>();
    gating_kernel<<<T_TOK / 8, 256>>>(inputs, gatew);
    scan_kernel<<<1, 1024>>>(out, out_size);
    zero_dropped_kernel<<<T_TOK * 32 / 256, 256>>>(out);
    ffn_gemm<1><<<dim3(DFFN / BN, CAPCT / BM, NEXP), 256>>>(inputs, w1, b1, nullptr);
    ffn_gemm<2><<<dim3(DMODEL / BN, CAPCT / BM, NEXP), 256>>>(nullptr, w2, b2, out);
}

// round 15
// speedup vs baseline: 1.0548x; 1.0168x over previous
#include <cuda_runtime.h>
#include <cstdint>

// ---------------- problem constants ----------------
#define T_TOK   8192
#define DMODEL  1024
#define NEXP    8
#define DFFN    4096
#define CAPCT   1280            // int(1.25*8192/8), even, >= 4
#define NSLOT   (NEXP*CAPCT)    // 10240

// ---------------- persistent scratch (device globals; no allocs) ----------------
__device__ int   g_top1[T_TOK];
__device__ float g_prob[T_TOK];
__device__ float g_me[NEXP];
__device__ int   g_kept[T_TOK];                  // 1 if token kept (rank < cap)
__device__ int   g_slot_tok[NSLOT];
__device__ float g_slot_w[NSLOT];
__device__ int   g_cnt_cap[NEXP];
__device__ float g_xd[(size_t)NSLOT * DMODEL];   // dispatched tokens, tf32-rounded
__device__ float g_h[(size_t)NSLOT * DFFN];      // GEMM1 output (gelu'd, tf32-rounded)

// ---------------- small helpers ----------------
__device__ __forceinline__ uint32_t f2tf(float f) {
    uint32_t r; asm("cvt.rna.tf32.f32 %0, %1;" : "=r"(r) : "f"(f)); return r;
}
__device__ __forceinline__ void cp16(uint32_t dst, const void* src) {
    asm volatile("cp.async.cg.shared.global [%0], [%1], 16;" :: "r"(dst), "l"(src));
}
__device__ __forceinline__ void cp_commit() { asm volatile("cp.async.commit_group;"); }
__device__ __forceinline__ void cp_wait1()  { asm volatile("cp.async.wait_group 1;"); }

__device__ __forceinline__ void mma_tf32(float* c, const uint32_t* a, uint32_t b0, uint32_t b1) {
    asm volatile(
        "mma.sync.aligned.m16n8k8.row.col.f32.tf32.tf32.f32 "
        "{%0,%1,%2,%3},{%4,%5,%6,%7},{%8,%9},{%0,%1,%2,%3};"
        : "+f"(c[0]), "+f"(c[1]), "+f"(c[2]), "+f"(c[3])
        : "r"(a[0]), "r"(a[1]), "r"(a[2]), "r"(a[3]), "r"(b0), "r"(b1));
}

__device__ __forceinline__ float gelu_f(float x) {
    float u = 0.7978845608028654f * (x + 0.044715f * x * x * x);
    float e = __expf(2.f * u);
    float t = 1.f - 2.f / (e + 1.f);
    return 0.5f * x * (1.f + t);
}

// ---------------- kernel 0a: init me accumulators ----------------
__global__ void init_me_kernel() {
    if (threadIdx.x < NEXP) g_me[threadIdx.x] = 0.f;
}

// ---------------- kernel 0b: zero only dropped-token rows (after scan) ----------------
__global__ __launch_bounds__(256) void zero_dropped_kernel(float* __restrict__ out) {
    int w = (blockIdx.x * blockDim.x + threadIdx.x) >> 5;   // one warp per token
    int lane = threadIdx.x & 31;
    if (w >= T_TOK || g_kept[w]) return;
    float4* row = (float4*)(out + (size_t)w * DMODEL);
    float4 z = make_float4(0.f, 0.f, 0.f, 0.f);
#pragma unroll
    for (int i = 0; i < 8; i++) row[lane + 32 * i] = z;
}

// ---------------- kernel 1: gating (1 warp per token) ----------------
__global__ __launch_bounds__(256) void gating_kernel(
    const float* __restrict__ tokens, const float* __restrict__ gw) {
    __shared__ float4 sgw[NEXP * 256];
    __shared__ float sme[NEXP];
    int tid = threadIdx.x;
    const float4* gw4 = (const float4*)gw;
    for (int i = tid; i < NEXP * 256; i += 256) sgw[i] = gw4[i];
    if (tid < NEXP) sme[tid] = 0.f;
    __syncthreads();

    int warp = tid >> 5, lane = tid & 31;
    int t = blockIdx.x * 8 + warp;
    const float4* tok = (const float4*)(tokens + (size_t)t * DMODEL);

    float acc[NEXP];
#pragma unroll
    for (int e = 0; e < NEXP; e++) acc[e] = 0.f;
#pragma unroll
    for (int j = 0; j < 8; j++) {
        float4 x = tok[lane + 32 * j];
#pragma unroll
        for (int e = 0; e < NEXP; e++) {
            float4 w = sgw[e * 256 + lane + 32 * j];
            acc[e] += x.x * w.x + x.y * w.y + x.z * w.z + x.w * w.w;
        }
    }
#pragma unroll
    for (int off = 16; off; off >>= 1)
#pragma unroll
        for (int e = 0; e < NEXP; e++)
            acc[e] += __shfl_xor_sync(0xffffffffu, acc[e], off);

    if (lane == 0) {
        float mx = acc[0]; int am = 0;
#pragma unroll
        for (int e = 1; e < NEXP; e++) if (acc[e] > mx) { mx = acc[e]; am = e; }
        float p[NEXP], s = 0.f;
#pragma unroll
        for (int e = 0; e < NEXP; e++) { p[e] = expf(acc[e] - mx); s += p[e]; }
        float inv = 1.f / s;
        g_top1[t] = am;
        g_prob[t] = p[am] * inv;
#pragma unroll
        for (int e = 0; e < NEXP; e++) atomicAdd(&sme[e], p[e] * inv);
    }
    __syncthreads();
    if (tid < NEXP) atomicAdd(&g_me[tid], sme[tid]);
}

// ---------------- kernel 2: routing scan (single block, exact cumsum order) ----------------
__global__ __launch_bounds__(1024) void scan_kernel(float* __restrict__ out, int out_size) {
    __shared__ int sh_wc[NEXP][32];
    __shared__ int sh_base[NEXP];
    __shared__ int sh_tot[NEXP];
    int tid = threadIdx.x, warp = tid >> 5, lane = tid & 31;
    unsigned ltmask = (1u << lane) - 1u;
    if (tid < NEXP) sh_base[tid] = 0;
    __syncthreads();

    for (int tile = 0; tile < T_TOK / 1024; tile++) {
        int t = tile * 1024 + tid;
        int e = g_top1[t];
        int rank_w = 0;
#pragma unroll
        for (int e8 = 0; e8 < NEXP; e8++) {
            unsigned m = __ballot_sync(0xffffffffu, e == e8);
            if (e == e8) rank_w = __popc(m & ltmask);
            if (lane == 0) sh_wc[e8][warp] = __popc(m);
        }
        __syncthreads();
        if (warp < NEXP) {
            int c = sh_wc[warp][lane];
            int s = c;
#pragma unroll
            for (int off = 1; off < 32; off <<= 1) {
                int v = __shfl_up_sync(0xffffffffu, s, off);
                if (lane >= off) s += v;
            }
            sh_wc[warp][lane] = s - c;
            if (lane == 31) sh_tot[warp] = s;
        }
        __syncthreads();
        int rank = sh_base[e] + sh_wc[e][warp] + rank_w;
        if (rank < CAPCT) {
            int slot = e * CAPCT + rank;
            g_slot_tok[slot] = t;
            g_slot_w[slot] = g_prob[t];
            g_kept[t] = 1;
        } else {
            g_kept[t] = 0;
        }
        __syncthreads();
        if (tid < NEXP) sh_base[tid] += sh_tot[tid];
        __syncthreads();
    }

    if (tid < NEXP) g_cnt_cap[tid] = min(sh_base[tid], CAPCT);
    __syncthreads();
    for (int i = tid; i < NSLOT; i += 1024) {
        int e = i / CAPCT, r = i - e * CAPCT;
        if (r >= min(sh_base[e], CAPCT)) { g_slot_tok[i] = -1; g_slot_w[i] = 0.f; }
    }
    if (tid == 0 && out_size > T_TOK * DMODEL) {
        float la = 0.f;
        const float invT = 1.f / (float)T_TOK;
#pragma unroll
        for (int e = 0; e < NEXP; e++)
            la += (g_me[e] * invT) * ((float)sh_base[e] * invT);
        out[T_TOK * DMODEL] = (float)NEXP * la;
    }
}

// ---------------- kernel 3: dispatch gather (tf32-rounded) ----------------
__global__ __launch_bounds__(256) void dispatch_kernel(const float* __restrict__ tokens) {
    int slot = blockIdx.x;
    int tok = g_slot_tok[slot];
    uint4* dst = (uint4*)(g_xd + (size_t)slot * DMODEL);
    if (tok < 0) {
        dst[threadIdx.x] = make_uint4(0u, 0u, 0u, 0u);
    } else {
        const float4* src = (const float4*)(tokens + (size_t)tok * DMODEL);
        float4 v = src[threadIdx.x];
        dst[threadIdx.x] = make_uint4(f2tf(v.x), f2tf(v.y), f2tf(v.z), f2tf(v.w));
    }
}

// ---- GEMM: 64x128x16 CTA tile, 32x32 warp tile (2x4 warps), 3-stage cp.async ----
// Exact R11 config (measured best: 959 us): 3 CTAs/SM, wait_group 1, cvt-free consumer.
#define BM 64
#define BN 128
#define BK 16
#define AST 20                   // padded A row stride (floats)
#define BST 136                  // padded B row stride (floats)
#define SA_STAGE (BM*AST)        // 1280 floats
#define SB_STAGE (BK*BST)        // 2176 floats
#define GSTAGES 3                // 41472 B static shared

// MODE 1: h = gelu(g_xd @ w1 + b1)         (K=1024, N=4096)
// MODE 2: out[token] = w * (g_h @ w2 + b2) (K=4096, N=1024), scatter
template <int MODE>
__global__ __launch_bounds__(256, 3) void ffn_gemm(
    const float* __restrict__ Wbase,
    const float* __restrict__ biasBase, float* __restrict__ Obase) {
    constexpr int N = (MODE == 1) ? DFFN : DMODEL;
    constexpr int K = (MODE == 1) ? DMODEL : DFFN;
    constexpr int KT = K / BK;

    const float* Abase = (MODE == 1) ? g_xd : g_h;   // device-side symbol ref
    constexpr int AROWSTRIDE = (MODE == 1) ? DMODEL : DFFN;

    const int e = blockIdx.z;
    const int mtile = blockIdx.y;
    const int ntile = blockIdx.x;
    if (mtile * BM >= g_cnt_cap[e]) return;

    __shared__ __align__(16) float sA[GSTAGES][SA_STAGE];
    __shared__ __align__(16) float sB[GSTAGES][SB_STAGE];
    uint32_t sA32 = (uint32_t)__cvta_generic_to_shared(&sA[0][0]);
    uint32_t sB32 = (uint32_t)__cvta_generic_to_shared(&sB[0][0]);

    const int tid = threadIdx.x;
    const int lane = tid & 31, warp = tid >> 5;
    const int wm = warp >> 2, wn = warp & 3;      // 2x4 warp grid: 32x32 per warp
    const int g = lane >> 2, tig = lane & 3;

    const float* W = Wbase + (size_t)e * K * N;
    const float* bias = biasBase + (size_t)e * N;
    const int slot0 = e * CAPCT + mtile * BM;

    // ---- producer assignments ----
    const int akc = tid & 3;
    const int arow = tid >> 2;
    const float* asrc = Abase + (size_t)(slot0 + arow) * AROWSTRIDE + akc * 4;
    const uint32_t adst = sA32 + (arow * AST + akc * 4) * 4;
    const int bc = tid & 31;
    const float* bsrc[2]; uint32_t bdst[2];
#pragma unroll
    for (int i = 0; i < 2; i++) {
        int brow = (tid >> 5) + i * 8;
        bsrc[i] = W + (size_t)brow * N + ntile * BN + bc * 4;
        bdst[i] = sB32 + (brow * BST + bc * 4) * 4;
    }

    auto issue = [&](int kt, int stage) {
        uint32_t ao = stage * (SA_STAGE * 4);
        uint32_t bo = stage * (SB_STAGE * 4);
        size_t kA = (size_t)kt * BK;
        size_t kB = (size_t)kt * BK * N;
        cp16(adst + ao, asrc + kA);
        cp16(bdst[0] + bo, bsrc[0] + kB);
        cp16(bdst[1] + bo, bsrc[1] + kB);
    };

    float acc[2][4][4];
#pragma unroll
    for (int mt = 0; mt < 2; mt++)
#pragma unroll
        for (int nt = 0; nt < 4; nt++)
#pragma unroll
            for (int c = 0; c < 4; c++) acc[mt][nt][c] = 0.f;

    issue(0, 0); cp_commit();
    issue(1, 1); cp_commit();

    int cur = 0, nxst = 2;
    for (int kt = 0; kt < KT; kt++) {
        cp_wait1();
        __syncthreads();
        int nx = kt + 2;
        if (nx < KT) issue(nx, nxst);
        cp_commit();

        const uint32_t* As = (const uint32_t*)&sA[cur][0];
        const uint32_t* Bs = (const uint32_t*)&sB[cur][0];
#pragma unroll
        for (int ks = 0; ks < 2; ks++) {
            uint32_t af[2][4];
#pragma unroll
            for (int mt = 0; mt < 2; mt++) {
                const uint32_t* p = As + (wm * 32 + mt * 16 + g) * AST + ks * 8 + tig;
                af[mt][0] = p[0];
                af[mt][1] = p[8 * AST];
                af[mt][2] = p[4];
                af[mt][3] = p[8 * AST + 4];
            }
#pragma unroll
            for (int nt = 0; nt < 4; nt++) {
                const uint32_t* p = Bs + (ks * 8 + tig) * BST + wn * 32 + nt * 8 + g;
                uint32_t b0 = p[0];
                uint32_t b1 = p[4 * BST];
                mma_tf32(acc[0][nt], af[0], b0, b1);
                mma_tf32(acc[1][nt], af[1], b0, b1);
            }
        }
        cur = (cur == GSTAGES - 1) ? 0 : cur + 1;
        nxst = (nxst == GSTAGES - 1) ? 0 : nxst + 1;
    }

    // ---- epilogue ----
    if (MODE == 1) {
#pragma unroll
        for (int mt = 0; mt < 2; mt++)
#pragma unroll
            for (int half = 0; half < 2; half++) {
                int rloc = wm * 32 + mt * 16 + g + half * 8;
                float* hrow = g_h + (size_t)(slot0 + rloc) * DFFN;
#pragma unroll
                for (int nt = 0; nt < 4; nt++) {
                    int col = ntile * BN + wn * 32 + nt * 8 + 2 * tig;
                    float2 bb = *(const float2*)(bias + col);
                    float v0 = gelu_f(acc[mt][nt][half * 2 + 0] + bb.x);
                    float v1 = gelu_f(acc[mt][nt][half * 2 + 1] + bb.y);
                    // pre-round h to tf32 so GEMM2's consumer needs no cvt
                    *(uint2*)(hrow + col) = make_uint2(f2tf(v0), f2tf(v1));
                }
            }
    } else {
#pragma unroll
        for (int mt = 0; mt < 2; mt++)
#pragma unroll
            for (int half = 0; half < 2; half++) {
                int rloc = wm * 32 + mt * 16 + g + half * 8;
                int slot = slot0 + rloc;
                int tok = g_slot_tok[slot];
                if (tok >= 0) {
                    float w = g_slot_w[slot];
                    float* orow = Obase + (size_t)tok * DMODEL;
#pragma unroll
                    for (int nt = 0; nt < 4; nt++) {
                        int col = ntile * BN + wn * 32 + nt * 8 + 2 * tig;
                        float2 bb = *(const float2*)(bias + col);
                        float v0 = (acc[mt][nt][half * 2 + 0] + bb.x) * w;
                        float v1 = (acc[mt][nt][half * 2 + 1] + bb.y) * w;
                        *(float2*)(orow + col) = make_float2(v0, v1);
                    }
                }
            }
    }
}

// ---------------- launch ----------------
extern "C" void kernel_launch(void* const* d_in, const int* in_sizes, int n_in,
                              void* d_out, int out_size) {
    const float* inputs = (const float*)d_in[0];
    const float* gatew  = (const float*)d_in[1];
    const float* w1     = (const float*)d_in[2];
    const float* b1     = (const float*)d_in[3];
    const float* w2     = (const float*)d_in[4];
    const float* b2     = (const float*)d_in[5];
    float* out = (float*)d_out;

    init_me_kernel<<<1, 32>>>();
    gating_kernel<<<T_TOK / 8, 256>>>(inputs, gatew);
    scan_kernel<<<1, 1024>>>(out, out_size);
    zero_dropped_kernel<<<T_TOK * 32 / 256, 256>>>(out);
    dispatch_kernel<<<NSLOT, 256>>>(inputs);
    ffn_gemm<1><<<dim3(DFFN / BN, CAPCT / BM, NEXP), 256>>>(w1, b1, nullptr);
    ffn_gemm<2><<<dim3(DMODEL / BN, CAPCT / BM, NEXP), 256>>>(w2, b2, out);
}